// round 1
// baseline (speedup 1.0000x reference)
#include <cuda_runtime.h>
#include <cstdint>

#define HIDDEN 4096
#define NH 32
#define NKV 8
#define HD 128
#define BS 16
#define SEQ 4096
#define QKV_N 6144           // 4096 q + 1024 k + 1024 v
#define KSPLIT 16
#define KC (HIDDEN / KSPLIT) // 256
#define SPLITS 16
#define CHUNK (SEQ / SPLITS) // 256

// ---------------- scratch (device globals; no allocs allowed) ----------------
__device__ float g_qkvpart[KSPLIT][BS * QKV_N];  // GEMM partials for q|k|v
__device__ float g_q[BS * NH * HD];              // rope'd q
__device__ float g_k[BS * NKV * HD];             // rope'd new k
__device__ float g_v[BS * NKV * HD];             // new v
__device__ float g_pacc[BS * NKV * SPLITS * 4 * HD]; // flash partial accumulators
__device__ float g_pm[BS * NKV * SPLITS * 4];        // partial max
__device__ float g_pl[BS * NKV * SPLITS * 4];        // partial sumexp
__device__ float g_attn[BS * NH * HD];           // attention output pre-wo
__device__ float g_opart[KSPLIT][BS * HIDDEN];   // wo GEMM partials

// ---------------- skinny GEMM: [16 x 4096] @ [4096 x N] with K-split ----------------
// grid (N/128, KSPLIT), block 128. Each thread owns one output column, 16 batch accs.
__global__ void gemm_kernel(const float* __restrict__ X, const float* __restrict__ W,
                            int N, int n_off, int NTOT, int to_qkv) {
    __shared__ float xs[BS][KC];
    const float* Xp = X ? X : g_attn;
    int n = blockIdx.x * 128 + threadIdx.x;
    int k0 = blockIdx.y * KC;

    for (int i = threadIdx.x; i < BS * KC; i += 128) {
        int b = i / KC, k = i % KC;
        xs[b][k] = Xp[b * HIDDEN + k0 + k];
    }
    __syncthreads();

    float acc[BS];
#pragma unroll
    for (int b = 0; b < BS; b++) acc[b] = 0.f;

    const float* Wp = W + (size_t)k0 * N + n;
    float w = *Wp;
    for (int k = 0; k < KC; k++) {
        float wn = (k + 1 < KC) ? Wp[(size_t)(k + 1) * N] : 0.f;
#pragma unroll
        for (int b = 0; b < BS; b++) acc[b] = fmaf(xs[b][k], w, acc[b]);
        w = wn;
    }

    float* part = to_qkv ? &g_qkvpart[0][0] : &g_opart[0][0];
    size_t base = (size_t)blockIdx.y * BS * NTOT;
#pragma unroll
    for (int b = 0; b < BS; b++)
        part[base + (size_t)b * NTOT + n_off + n] = acc[b];
}

// ---------------- reduce GEMM partials + RoPE + stage k/v ----------------
// grid 16 (batch), block 256
__global__ void rope_reduce_kernel(const float* __restrict__ rope_cache,
                                   const int* __restrict__ last_pos) {
    __shared__ float qkv[QKV_N];
    int b = blockIdx.x;
    for (int i = threadIdx.x; i < QKV_N; i += blockDim.x) {
        float s = 0.f;
#pragma unroll
        for (int ks = 0; ks < KSPLIT; ks++) s += g_qkvpart[ks][b * QKV_N + i];
        qkv[i] = s;
    }
    __syncthreads();

    int lp = last_pos[b];
    const float* rc = rope_cache + (size_t)lp * HD;  // [64][2] cos/sin
    for (int i = threadIdx.x; i < QKV_N; i += blockDim.x) {
        float val;
        if (i < (NH + NKV) * HD) {  // rope on q (first 4096) and k (next 1024)
            int dd = i % HD;
            int pi = dd >> 1;
            float c = rc[2 * pi], s = rc[2 * pi + 1];
            if ((dd & 1) == 0) val = qkv[i] * c - qkv[i + 1] * s;
            else               val = qkv[i] * c + qkv[i - 1] * s;
        } else {
            val = qkv[i];
        }
        if (i < NH * HD)                  g_q[b * (NH * HD) + i] = val;
        else if (i < (NH + NKV) * HD)     g_k[b * (NKV * HD) + (i - NH * HD)] = val;
        else                              g_v[b * (NKV * HD) + (i - (NH + NKV) * HD)] = val;
    }
}

// ---------------- fused cache-copy + flash-decode attention ----------------
// grid (SPLITS, NKV, BS), block 256. Each block: one 256-row KV chunk for one (b,kv).
// Streams K rows (HBM read -> upd_k write + 4 q-dots), then V rows (read -> upd_v
// write + weighted accumulation). last_pos row substituted with fresh k/v.
__global__ void attn_kernel(const float* __restrict__ cache_k,
                            const float* __restrict__ cache_v,
                            const float* __restrict__ mask,
                            const int* __restrict__ last_pos,
                            float* __restrict__ out_k, float* __restrict__ out_v) {
    __shared__ float sq[4][HD];
    __shared__ float sc[4][CHUNK];
    __shared__ float sm[4], sl[4];

    int sp = blockIdx.x, kv = blockIdx.y, b = blockIdx.z;
    int tid = threadIdx.x;
    int j0 = sp * CHUNK;
    int lp = last_pos[b];

    for (int i = tid; i < 4 * HD; i += 256) {
        int h = i / HD, d = i % HD;
        sq[h][d] = g_q[b * (NH * HD) + (kv * 4 + h) * HD + d];
    }
    __syncthreads();

    const float scale = 0.08838834764831845f; // 1/sqrt(128)
    int w = tid >> 5, l = tid & 31;

    // ---- K pass: one warp per row; copy row to upd_k; 4 dot products ----
    for (int jj = w; jj < CHUNK; jj += 8) {
        int j = j0 + jj;
        size_t row = ((size_t)(b * SEQ + j) * NKV + kv) * HD;
        const float4* src = (j == lp)
            ? (const float4*)(g_k + (b * NKV + kv) * HD)
            : (const float4*)(cache_k + row);
        float4 kk = src[l];
        ((float4*)(out_k + row))[l] = kk;

        float s0 = sq[0][4*l] * kk.x + sq[0][4*l+1] * kk.y + sq[0][4*l+2] * kk.z + sq[0][4*l+3] * kk.w;
        float s1 = sq[1][4*l] * kk.x + sq[1][4*l+1] * kk.y + sq[1][4*l+2] * kk.z + sq[1][4*l+3] * kk.w;
        float s2 = sq[2][4*l] * kk.x + sq[2][4*l+1] * kk.y + sq[2][4*l+2] * kk.z + sq[2][4*l+3] * kk.w;
        float s3 = sq[3][4*l] * kk.x + sq[3][4*l+1] * kk.y + sq[3][4*l+2] * kk.z + sq[3][4*l+3] * kk.w;
#pragma unroll
        for (int off = 16; off; off >>= 1) {
            s0 += __shfl_xor_sync(0xffffffffu, s0, off);
            s1 += __shfl_xor_sync(0xffffffffu, s1, off);
            s2 += __shfl_xor_sync(0xffffffffu, s2, off);
            s3 += __shfl_xor_sync(0xffffffffu, s3, off);
        }
        if (l == 0) {
            float mk = mask[b * SEQ + j];
            sc[0][jj] = s0 * scale + mk;
            sc[1][jj] = s1 * scale + mk;
            sc[2][jj] = s2 * scale + mk;
            sc[3][jj] = s3 * scale + mk;
        }
    }
    __syncthreads();

    // ---- chunk-local softmax (partial): warps 0..3 each own one head ----
    if (w < 4) {
        float mx = -1e30f;
        for (int jj = l; jj < CHUNK; jj += 32) mx = fmaxf(mx, sc[w][jj]);
#pragma unroll
        for (int off = 16; off; off >>= 1)
            mx = fmaxf(mx, __shfl_xor_sync(0xffffffffu, mx, off));
        float sum = 0.f;
        for (int jj = l; jj < CHUNK; jj += 32) {
            float p = __expf(sc[w][jj] - mx);
            sc[w][jj] = p;
            sum += p;
        }
#pragma unroll
        for (int off = 16; off; off >>= 1)
            sum += __shfl_xor_sync(0xffffffffu, sum, off);
        if (l == 0) { sm[w] = mx; sl[w] = sum; }
    }
    __syncthreads();

    // ---- V pass: thread -> (head-pair, dim); copy rows to upd_v; accumulate ----
    int d = tid & 127, hp = tid >> 7;  // hp=0 -> heads 0,1 ; hp=1 -> heads 2,3
    float a0 = 0.f, a1 = 0.f;
#pragma unroll 4
    for (int jj = 0; jj < CHUNK; jj++) {
        int j = j0 + jj;
        size_t row = ((size_t)(b * SEQ + j) * NKV + kv) * HD;
        const float* vr = (j == lp) ? (g_v + (b * NKV + kv) * HD) : (cache_v + row);
        float v = vr[d];
        if (hp == 0) out_v[row + d] = v;
        a0 = fmaf(sc[2 * hp][jj], v, a0);
        a1 = fmaf(sc[2 * hp + 1][jj], v, a1);
    }
    size_t pbase = ((size_t)(b * NKV + kv) * SPLITS + sp) * 4;
    g_pacc[(pbase + 2 * hp) * HD + d]     = a0;
    g_pacc[(pbase + 2 * hp + 1) * HD + d] = a1;
    if (tid < 4) { g_pm[pbase + tid] = sm[tid]; g_pl[pbase + tid] = sl[tid]; }
}

// ---------------- combine split partials ----------------
// grid (NH, BS), block 128
__global__ void combine_kernel() {
    int h = blockIdx.x, b = blockIdx.y, d = threadIdx.x;
    int kv = h >> 2, r = h & 3;
    size_t base = (size_t)(b * NKV + kv) * SPLITS;
    float M = -1e30f;
#pragma unroll
    for (int s = 0; s < SPLITS; s++) M = fmaxf(M, g_pm[(base + s) * 4 + r]);
    float L = 0.f, acc = 0.f;
#pragma unroll
    for (int s = 0; s < SPLITS; s++) {
        float wgt = __expf(g_pm[(base + s) * 4 + r] - M);
        L += g_pl[(base + s) * 4 + r] * wgt;
        acc += g_pacc[((base + s) * 4 + r) * HD + d] * wgt;
    }
    g_attn[b * (NH * HD) + h * HD + d] = acc / L;
}

// ---------------- reduce wo-GEMM partials -> final out ----------------
__global__ void reduce_out_kernel(float* __restrict__ out) {
    int i = blockIdx.x * 256 + threadIdx.x;
    float s = 0.f;
#pragma unroll
    for (int ks = 0; ks < KSPLIT; ks++) s += g_opart[ks][i];
    out[i] = s;
}

// ---------------- launch ----------------
extern "C" void kernel_launch(void* const* d_in, const int* in_sizes, int n_in,
                              void* d_out, int out_size) {
    const float* x       = (const float*)d_in[0];
    const float* mask    = (const float*)d_in[1];
    const float* rope    = (const float*)d_in[2];
    const float* wq      = (const float*)d_in[3];
    const float* wk      = (const float*)d_in[4];
    const float* wv      = (const float*)d_in[5];
    const float* wo      = (const float*)d_in[6];
    const float* cache_k = (const float*)d_in[7];
    const float* cache_v = (const float*)d_in[8];
    const int*   last_pos = (const int*)d_in[9];

    float* out   = (float*)d_out;
    float* out_k = out + (size_t)BS * HIDDEN;                 // after [16,1,4096]
    float* out_v = out_k + (size_t)BS * SEQ * NKV * HD;       // after upd_k

    // 1-3: qkv projection (partials, K-split)
    gemm_kernel<<<dim3(HIDDEN / 128, KSPLIT), 128>>>(x, wq, HIDDEN, 0, QKV_N, 1);
    gemm_kernel<<<dim3((NKV * HD) / 128, KSPLIT), 128>>>(x, wk, NKV * HD, NH * HD, QKV_N, 1);
    gemm_kernel<<<dim3((NKV * HD) / 128, KSPLIT), 128>>>(x, wv, NKV * HD, (NH + NKV) * HD, QKV_N, 1);

    // 4: reduce + rope + stage new k/v
    rope_reduce_kernel<<<BS, 256>>>(rope, last_pos);

    // 5: fused cache copy + flash-decode attention
    attn_kernel<<<dim3(SPLITS, NKV, BS), 256>>>(cache_k, cache_v, mask, last_pos, out_k, out_v);

    // 6: combine flash partials
    combine_kernel<<<dim3(NH, BS), HD>>>();

    // 7: output projection (partials) + 8: reduce into d_out
    gemm_kernel<<<dim3(HIDDEN / 128, KSPLIT), 128>>>(nullptr, wo, HIDDEN, 0, HIDDEN, 0);
    reduce_out_kernel<<<(BS * HIDDEN) / 256, 256>>>(out);
}

// round 2
// speedup vs baseline: 1.6226x; 1.6226x over previous
#include <cuda_runtime.h>
#include <cstdint>

#define HIDDEN 4096
#define NH 32
#define NKV 8
#define HD 128
#define BS 16
#define SEQ 4096
#define QKV_N 6144           // 4096 q + 1024 k + 1024 v
#define KSPLIT 16
#define KC (HIDDEN / KSPLIT) // 256
#define SPLITS 32
#define CHUNK (SEQ / SPLITS) // 128

// ---------------- scratch (device globals; no allocs allowed) ----------------
__device__ float g_qkvpart[KSPLIT][BS * QKV_N];  // GEMM partials for q|k|v
__device__ float g_q[BS * NH * HD];              // rope'd q
__device__ float g_k[BS * NKV * HD];             // rope'd new k
__device__ float g_v[BS * NKV * HD];             // new v
__device__ float g_pacc[BS * NKV * SPLITS * 4 * HD]; // flash partial accumulators
__device__ float g_pm[BS * NKV * SPLITS * 4];        // partial max
__device__ float g_pl[BS * NKV * SPLITS * 4];        // partial sumexp
__device__ float g_attn[BS * NH * HD];           // attention output pre-wo
__device__ float g_opart[KSPLIT][BS * HIDDEN];   // wo GEMM partials

// ---------------- fused qkv skinny GEMM: [16 x 4096] @ [4096 x 6144] ----------------
// grid (QKV_N/128, KSPLIT), block 128. Block's 128 columns never straddle wq/wk/wv.
__global__ void qkv_gemm_kernel(const float* __restrict__ X,
                                const float* __restrict__ wq,
                                const float* __restrict__ wk,
                                const float* __restrict__ wv) {
    __shared__ float xs[BS][KC];
    int ng = blockIdx.x * 128 + threadIdx.x;   // global col in [0, 6144)
    int k0 = blockIdx.y * KC;

    const float* W; int col, Nw;
    if (ng < NH * HD)              { W = wq; col = ng;            Nw = NH * HD; }
    else if (ng < (NH + NKV) * HD) { W = wk; col = ng - NH * HD;  Nw = NKV * HD; }
    else                           { W = wv; col = ng - (NH + NKV) * HD; Nw = NKV * HD; }

    for (int i = threadIdx.x; i < BS * KC; i += 128) {
        int b = i / KC, k = i % KC;
        xs[b][k] = X[b * HIDDEN + k0 + k];
    }
    __syncthreads();

    float acc[BS];
#pragma unroll
    for (int b = 0; b < BS; b++) acc[b] = 0.f;

    const float* Wp = W + (size_t)k0 * Nw + col;
    float w = *Wp;
    for (int k = 0; k < KC; k++) {
        float wn = (k + 1 < KC) ? Wp[(size_t)(k + 1) * Nw] : 0.f;
#pragma unroll
        for (int b = 0; b < BS; b++) acc[b] = fmaf(xs[b][k], w, acc[b]);
        w = wn;
    }

    size_t base = (size_t)blockIdx.y * BS * QKV_N;
#pragma unroll
    for (int b = 0; b < BS; b++)
        g_qkvpart[0][base + (size_t)b * QKV_N + ng] = acc[b];
}

// ---------------- wo skinny GEMM: g_attn [16 x 4096] @ wo [4096 x 4096] ----------------
__global__ void wo_gemm_kernel(const float* __restrict__ W) {
    __shared__ float xs[BS][KC];
    int n = blockIdx.x * 128 + threadIdx.x;
    int k0 = blockIdx.y * KC;

    for (int i = threadIdx.x; i < BS * KC; i += 128) {
        int b = i / KC, k = i % KC;
        xs[b][k] = g_attn[b * HIDDEN + k0 + k];
    }
    __syncthreads();

    float acc[BS];
#pragma unroll
    for (int b = 0; b < BS; b++) acc[b] = 0.f;

    const float* Wp = W + (size_t)k0 * HIDDEN + n;
    float w = *Wp;
    for (int k = 0; k < KC; k++) {
        float wn = (k + 1 < KC) ? Wp[(size_t)(k + 1) * HIDDEN] : 0.f;
#pragma unroll
        for (int b = 0; b < BS; b++) acc[b] = fmaf(xs[b][k], w, acc[b]);
        w = wn;
    }

    size_t base = (size_t)blockIdx.y * BS * HIDDEN;
#pragma unroll
    for (int b = 0; b < BS; b++)
        g_opart[0][base + (size_t)b * HIDDEN + n] = acc[b];
}

// ---------------- parallel reduce partials + RoPE + stage q/k/v ----------------
// one thread per element pair; grid = BS*QKV_N/2/256 = 192 blocks
__global__ void rope_reduce_kernel(const float* __restrict__ rope_cache,
                                   const int* __restrict__ last_pos) {
    int idx = blockIdx.x * 256 + threadIdx.x;       // pair index
    int b = idx / (QKV_N / 2);
    int i = (idx % (QKV_N / 2)) * 2;                // even element index within batch row

    float v0 = 0.f, v1 = 0.f;
#pragma unroll
    for (int ks = 0; ks < KSPLIT; ks++) {
        const float2 s = *(const float2*)&g_qkvpart[ks][b * QKV_N + i];
        v0 += s.x; v1 += s.y;
    }

    float o0 = v0, o1 = v1;
    if (i < (NH + NKV) * HD) {   // rope on q and k
        int lp = last_pos[b];
        int pi = (i % HD) >> 1;
        const float2 cs = *(const float2*)(rope_cache + (size_t)lp * HD + 2 * pi);
        o0 = v0 * cs.x - v1 * cs.y;
        o1 = v1 * cs.x + v0 * cs.y;
    }

    float* dst;
    if (i < NH * HD)                 dst = g_q + b * (NH * HD) + i;
    else if (i < (NH + NKV) * HD)    dst = g_k + b * (NKV * HD) + (i - NH * HD);
    else                             dst = g_v + b * (NKV * HD) + (i - (NH + NKV) * HD);
    dst[0] = o0;
    dst[1] = o1;
}

// ---------------- fused cache-copy + flash-decode attention ----------------
// grid (SPLITS, NKV, BS) = 4096 blocks, block 256 (8 warps).
__global__ void attn_kernel(const float* __restrict__ cache_k,
                            const float* __restrict__ cache_v,
                            const float* __restrict__ mask,
                            const int* __restrict__ last_pos,
                            float* __restrict__ out_k, float* __restrict__ out_v) {
    __shared__ float sq[4][HD];
    __shared__ float sc[4][CHUNK];
    __shared__ float sacc[8][4][HD];   // per-warp V accumulators (16 KB)
    __shared__ float sm[4], sl[4];

    int sp = blockIdx.x, kv = blockIdx.y, b = blockIdx.z;
    int tid = threadIdx.x;
    int j0 = sp * CHUNK;
    int lp = last_pos[b];
    int w = tid >> 5, l = tid & 31;

    for (int i = tid; i < 4 * HD; i += 256) {
        int h = i / HD, d = i % HD;
        sq[h][d] = g_q[b * (NH * HD) + (kv * 4 + h) * HD + d];
    }
    __syncthreads();

    const float scale = 0.08838834764831845f; // 1/sqrt(128)
    const float4* newk = (const float4*)(g_k + (b * NKV + kv) * HD);
    const float4* newv = (const float4*)(g_v + (b * NKV + kv) * HD);

    // ---- K pass: warp per row, 2 rows in flight; copy to upd_k; 4 head dots ----
    for (int jj = w; jj < CHUNK; jj += 16) {
        int jA = j0 + jj, jB = j0 + jj + 8;
        size_t rowA = ((size_t)(b * SEQ + jA) * NKV + kv) * HD;
        size_t rowB = ((size_t)(b * SEQ + jB) * NKV + kv) * HD;
        const float4* srcA = (jA == lp) ? newk : (const float4*)(cache_k + rowA);
        const float4* srcB = (jB == lp) ? newk : (const float4*)(cache_k + rowB);
        float4 kA = srcA[l];
        float4 kB = srcB[l];
        ((float4*)(out_k + rowA))[l] = kA;
        ((float4*)(out_k + rowB))[l] = kB;

        float sA[4], sB[4];
#pragma unroll
        for (int h = 0; h < 4; h++) {
            sA[h] = sq[h][4*l] * kA.x + sq[h][4*l+1] * kA.y + sq[h][4*l+2] * kA.z + sq[h][4*l+3] * kA.w;
            sB[h] = sq[h][4*l] * kB.x + sq[h][4*l+1] * kB.y + sq[h][4*l+2] * kB.z + sq[h][4*l+3] * kB.w;
        }
#pragma unroll
        for (int off = 16; off; off >>= 1) {
#pragma unroll
            for (int h = 0; h < 4; h++) {
                sA[h] += __shfl_xor_sync(0xffffffffu, sA[h], off);
                sB[h] += __shfl_xor_sync(0xffffffffu, sB[h], off);
            }
        }
        if (l == 0) {
            float mA = mask[b * SEQ + jA];
            float mB = mask[b * SEQ + jB];
#pragma unroll
            for (int h = 0; h < 4; h++) {
                sc[h][jj]     = sA[h] * scale + mA;
                sc[h][jj + 8] = sB[h] * scale + mB;
            }
        }
    }
    __syncthreads();

    // ---- chunk-local softmax (partial): warps 0..3 each own one head ----
    if (w < 4) {
        float mx = -1e30f;
        for (int jj = l; jj < CHUNK; jj += 32) mx = fmaxf(mx, sc[w][jj]);
#pragma unroll
        for (int off = 16; off; off >>= 1)
            mx = fmaxf(mx, __shfl_xor_sync(0xffffffffu, mx, off));
        float sum = 0.f;
        for (int jj = l; jj < CHUNK; jj += 32) {
            float p = __expf(sc[w][jj] - mx);
            sc[w][jj] = p;
            sum += p;
        }
#pragma unroll
        for (int off = 16; off; off >>= 1)
            sum += __shfl_xor_sync(0xffffffffu, sum, off);
        if (l == 0) { sm[w] = mx; sl[w] = sum; }
    }
    __syncthreads();

    // ---- V pass: warp per row, 2 rows in flight; copy to upd_v; accumulate ----
    float4 acc[4];
#pragma unroll
    for (int h = 0; h < 4; h++) acc[h] = make_float4(0.f, 0.f, 0.f, 0.f);

    for (int jj = w; jj < CHUNK; jj += 16) {
        int jA = j0 + jj, jB = j0 + jj + 8;
        size_t rowA = ((size_t)(b * SEQ + jA) * NKV + kv) * HD;
        size_t rowB = ((size_t)(b * SEQ + jB) * NKV + kv) * HD;
        const float4* srcA = (jA == lp) ? newv : (const float4*)(cache_v + rowA);
        const float4* srcB = (jB == lp) ? newv : (const float4*)(cache_v + rowB);
        float4 vA = srcA[l];
        float4 vB = srcB[l];
        ((float4*)(out_v + rowA))[l] = vA;
        ((float4*)(out_v + rowB))[l] = vB;

#pragma unroll
        for (int h = 0; h < 4; h++) {
            float pA = sc[h][jj], pB = sc[h][jj + 8];
            acc[h].x = fmaf(pA, vA.x, fmaf(pB, vB.x, acc[h].x));
            acc[h].y = fmaf(pA, vA.y, fmaf(pB, vB.y, acc[h].y));
            acc[h].z = fmaf(pA, vA.z, fmaf(pB, vB.z, acc[h].z));
            acc[h].w = fmaf(pA, vA.w, fmaf(pB, vB.w, acc[h].w));
        }
    }
#pragma unroll
    for (int h = 0; h < 4; h++)
        *(float4*)&sacc[w][h][4 * l] = acc[h];
    __syncthreads();

    // ---- cross-warp reduction of V accumulators + write partials ----
    size_t pbase = ((size_t)(b * NKV + kv) * SPLITS + sp) * 4;
    for (int o = tid; o < 4 * HD; o += 256) {
        int h = o / HD, d = o % HD;
        float s = 0.f;
#pragma unroll
        for (int ww = 0; ww < 8; ww++) s += sacc[ww][h][d];
        g_pacc[(pbase + h) * HD + d] = s;
    }
    if (tid < 4) { g_pm[pbase + tid] = sm[tid]; g_pl[pbase + tid] = sl[tid]; }
}

// ---------------- combine split partials ----------------
// grid (NH, BS), block 128
__global__ void combine_kernel() {
    int h = blockIdx.x, b = blockIdx.y, d = threadIdx.x;
    int kv = h >> 2, r = h & 3;
    size_t base = (size_t)(b * NKV + kv) * SPLITS;
    float M = -1e30f;
#pragma unroll
    for (int s = 0; s < SPLITS; s++) M = fmaxf(M, g_pm[(base + s) * 4 + r]);
    float L = 0.f, acc = 0.f;
#pragma unroll
    for (int s = 0; s < SPLITS; s++) {
        float wgt = __expf(g_pm[(base + s) * 4 + r] - M);
        L += g_pl[(base + s) * 4 + r] * wgt;
        acc += g_pacc[((base + s) * 4 + r) * HD + d] * wgt;
    }
    g_attn[b * (NH * HD) + h * HD + d] = acc / L;
}

// ---------------- reduce wo-GEMM partials -> final out ----------------
__global__ void reduce_out_kernel(float* __restrict__ out) {
    int i = blockIdx.x * 256 + threadIdx.x;
    float s = 0.f;
#pragma unroll
    for (int ks = 0; ks < KSPLIT; ks++) s += g_opart[ks][i];
    out[i] = s;
}

// ---------------- launch ----------------
extern "C" void kernel_launch(void* const* d_in, const int* in_sizes, int n_in,
                              void* d_out, int out_size) {
    const float* x       = (const float*)d_in[0];
    const float* mask    = (const float*)d_in[1];
    const float* rope    = (const float*)d_in[2];
    const float* wq      = (const float*)d_in[3];
    const float* wk      = (const float*)d_in[4];
    const float* wv      = (const float*)d_in[5];
    const float* wo      = (const float*)d_in[6];
    const float* cache_k = (const float*)d_in[7];
    const float* cache_v = (const float*)d_in[8];
    const int*   last_pos = (const int*)d_in[9];

    float* out   = (float*)d_out;
    float* out_k = out + (size_t)BS * HIDDEN;
    float* out_v = out_k + (size_t)BS * SEQ * NKV * HD;

    qkv_gemm_kernel<<<dim3(QKV_N / 128, KSPLIT), 128>>>(x, wq, wk, wv);
    rope_reduce_kernel<<<(BS * QKV_N / 2) / 256, 256>>>(rope, last_pos);
    attn_kernel<<<dim3(SPLITS, NKV, BS), 256>>>(cache_k, cache_v, mask, last_pos, out_k, out_v);
    combine_kernel<<<dim3(NH, BS), HD>>>();
    wo_gemm_kernel<<<dim3(HIDDEN / 128, KSPLIT), 128>>>(wo);
    reduce_out_kernel<<<(BS * HIDDEN) / 256, 256>>>(out);
}

// round 3
// speedup vs baseline: 1.6984x; 1.0467x over previous
#include <cuda_runtime.h>
#include <cstdint>

#define HIDDEN 4096
#define NH 32
#define NKV 8
#define HD 128
#define BS 16
#define SEQ 4096
#define QKV_N 6144           // 4096 q + 1024 k + 1024 v
#define KSPLIT 16
#define KC (HIDDEN / KSPLIT) // 256
#define SPLITS 32
#define CHUNK (SEQ / SPLITS) // 128

// ---------------- scratch (device globals; no allocs allowed) ----------------
__device__ float g_qkvpart[KSPLIT][BS * QKV_N];  // GEMM partials for q|k|v
__device__ float g_q[BS * NH * HD];              // rope'd q
__device__ float g_k[BS * NKV * HD];             // rope'd new k
__device__ float g_v[BS * NKV * HD];             // new v
__device__ float g_pacc[BS * NKV * SPLITS * 4 * HD]; // flash partial accumulators
__device__ float g_pm[BS * NKV * SPLITS * 4];        // partial max
__device__ float g_pl[BS * NKV * SPLITS * 4];        // partial sumexp
__device__ float g_attn[BS * NH * HD];           // attention output pre-wo
__device__ float g_opart[KSPLIT][BS * HIDDEN];   // wo GEMM partials

// ---------------- fused qkv skinny GEMM: [16 x 4096] @ [4096 x 6144] ----------------
__global__ void qkv_gemm_kernel(const float* __restrict__ X,
                                const float* __restrict__ wq,
                                const float* __restrict__ wk,
                                const float* __restrict__ wv) {
    __shared__ float xs[BS][KC];
    int ng = blockIdx.x * 128 + threadIdx.x;   // global col in [0, 6144)
    int k0 = blockIdx.y * KC;

    const float* W; int col, Nw;
    if (ng < NH * HD)              { W = wq; col = ng;            Nw = NH * HD; }
    else if (ng < (NH + NKV) * HD) { W = wk; col = ng - NH * HD;  Nw = NKV * HD; }
    else                           { W = wv; col = ng - (NH + NKV) * HD; Nw = NKV * HD; }

    for (int i = threadIdx.x; i < BS * KC; i += 128) {
        int b = i / KC, k = i % KC;
        xs[b][k] = X[b * HIDDEN + k0 + k];
    }
    __syncthreads();

    float acc[BS];
#pragma unroll
    for (int b = 0; b < BS; b++) acc[b] = 0.f;

    const float* Wp = W + (size_t)k0 * Nw + col;
    float w = *Wp;
    for (int k = 0; k < KC; k++) {
        float wn = (k + 1 < KC) ? Wp[(size_t)(k + 1) * Nw] : 0.f;
#pragma unroll
        for (int b = 0; b < BS; b++) acc[b] = fmaf(xs[b][k], w, acc[b]);
        w = wn;
    }

    size_t base = (size_t)blockIdx.y * BS * QKV_N;
#pragma unroll
    for (int b = 0; b < BS; b++)
        g_qkvpart[0][base + (size_t)b * QKV_N + ng] = acc[b];
}

// ---------------- wo skinny GEMM: g_attn [16 x 4096] @ wo [4096 x 4096] ----------------
__global__ void wo_gemm_kernel(const float* __restrict__ W) {
    __shared__ float xs[BS][KC];
    int n = blockIdx.x * 128 + threadIdx.x;
    int k0 = blockIdx.y * KC;

    for (int i = threadIdx.x; i < BS * KC; i += 128) {
        int b = i / KC, k = i % KC;
        xs[b][k] = g_attn[b * HIDDEN + k0 + k];
    }
    __syncthreads();

    float acc[BS];
#pragma unroll
    for (int b = 0; b < BS; b++) acc[b] = 0.f;

    const float* Wp = W + (size_t)k0 * HIDDEN + n;
    float w = *Wp;
    for (int k = 0; k < KC; k++) {
        float wn = (k + 1 < KC) ? Wp[(size_t)(k + 1) * HIDDEN] : 0.f;
#pragma unroll
        for (int b = 0; b < BS; b++) acc[b] = fmaf(xs[b][k], w, acc[b]);
        w = wn;
    }

    size_t base = (size_t)blockIdx.y * BS * HIDDEN;
#pragma unroll
    for (int b = 0; b < BS; b++)
        g_opart[0][base + (size_t)b * HIDDEN + n] = acc[b];
}

// ---------------- parallel reduce partials + RoPE + stage q/k/v ----------------
__global__ void rope_reduce_kernel(const float* __restrict__ rope_cache,
                                   const int* __restrict__ last_pos) {
    int idx = blockIdx.x * 256 + threadIdx.x;       // pair index
    int b = idx / (QKV_N / 2);
    int i = (idx % (QKV_N / 2)) * 2;

    float v0 = 0.f, v1 = 0.f;
#pragma unroll
    for (int ks = 0; ks < KSPLIT; ks++) {
        const float2 s = *(const float2*)&g_qkvpart[ks][b * QKV_N + i];
        v0 += s.x; v1 += s.y;
    }

    float o0 = v0, o1 = v1;
    if (i < (NH + NKV) * HD) {   // rope on q and k
        int lp = last_pos[b];
        int pi = (i % HD) >> 1;
        const float2 cs = *(const float2*)(rope_cache + (size_t)lp * HD + 2 * pi);
        o0 = v0 * cs.x - v1 * cs.y;
        o1 = v1 * cs.x + v0 * cs.y;
    }

    float* dst;
    if (i < NH * HD)                 dst = g_q + b * (NH * HD) + i;
    else if (i < (NH + NKV) * HD)    dst = g_k + b * (NKV * HD) + (i - NH * HD);
    else                             dst = g_v + b * (NKV * HD) + (i - (NH + NKV) * HD);
    dst[0] = o0;
    dst[1] = o1;
}

// ---------------- single-pass fused cache-copy + online-softmax flash decode ----------------
// grid (SPLITS, NKV, BS) = 4096 blocks, 256 threads (8 warps).
// Each warp streams K+V rows together (4 independent float4 loads in flight),
// maintains per-head online softmax state, then block-combines 8 warp partials.
__global__ void __launch_bounds__(256, 3)
attn_kernel(const float* __restrict__ cache_k,
            const float* __restrict__ cache_v,
            const float* __restrict__ mask,
            const int* __restrict__ last_pos,
            float* __restrict__ out_k, float* __restrict__ out_v) {
    __shared__ float sq[4][HD];
    __shared__ float sacc[8][4][HD];   // per-warp V accumulators (16 KB)
    __shared__ float smx[8][4], slx[8][4];

    int sp = blockIdx.x, kv = blockIdx.y, b = blockIdx.z;
    int tid = threadIdx.x;
    int j0 = sp * CHUNK;
    int lp = last_pos[b];
    int w = tid >> 5, l = tid & 31;

    for (int i = tid; i < 4 * HD; i += 256) {
        int h = i / HD, d = i % HD;
        sq[h][d] = g_q[b * (NH * HD) + (kv * 4 + h) * HD + d];
    }
    __syncthreads();

    float4 qr[4];
#pragma unroll
    for (int h = 0; h < 4; h++) qr[h] = *(float4*)&sq[h][4 * l];

    const float scale = 0.08838834764831845f; // 1/sqrt(128)
    const float4* newk = (const float4*)(g_k + (b * NKV + kv) * HD);
    const float4* newv = (const float4*)(g_v + (b * NKV + kv) * HD);

    float4 acc[4];
    float m[4], lsum[4];
#pragma unroll
    for (int h = 0; h < 4; h++) {
        acc[h] = make_float4(0.f, 0.f, 0.f, 0.f);
        m[h] = -1e30f;
        lsum[h] = 0.f;
    }

#pragma unroll 1
    for (int it = 0; it < CHUNK / 16; it++) {
        int jA = j0 + it * 16 + 2 * w;
        int jB = jA + 1;
        size_t rowA = ((size_t)(b * SEQ + jA) * NKV + kv) * HD;
        size_t rowB = rowA + (size_t)NKV * HD;

        const float4* kAp = (jA == lp) ? newk : (const float4*)(cache_k + rowA);
        const float4* kBp = (jB == lp) ? newk : (const float4*)(cache_k + rowB);
        const float4* vAp = (jA == lp) ? newv : (const float4*)(cache_v + rowA);
        const float4* vBp = (jB == lp) ? newv : (const float4*)(cache_v + rowB);

        float4 kA = __ldcs(kAp + l);
        float4 kB = __ldcs(kBp + l);
        float4 vA = __ldcs(vAp + l);
        float4 vB = __ldcs(vBp + l);

        __stcs(((float4*)(out_k + rowA)) + l, kA);
        __stcs(((float4*)(out_k + rowB)) + l, kB);
        __stcs(((float4*)(out_v + rowA)) + l, vA);
        __stcs(((float4*)(out_v + rowB)) + l, vB);

        float sA[4], sB[4];
#pragma unroll
        for (int h = 0; h < 4; h++) {
            sA[h] = qr[h].x * kA.x + qr[h].y * kA.y + qr[h].z * kA.z + qr[h].w * kA.w;
            sB[h] = qr[h].x * kB.x + qr[h].y * kB.y + qr[h].z * kB.z + qr[h].w * kB.w;
        }
#pragma unroll
        for (int off = 16; off; off >>= 1) {
#pragma unroll
            for (int h = 0; h < 4; h++) {
                sA[h] += __shfl_xor_sync(0xffffffffu, sA[h], off);
                sB[h] += __shfl_xor_sync(0xffffffffu, sB[h], off);
            }
        }

        float mA = __ldg(mask + b * SEQ + jA);
        float mB = __ldg(mask + b * SEQ + jB);

#pragma unroll
        for (int h = 0; h < 4; h++) {
            float scA = sA[h] * scale + mA;
            float scB = sB[h] * scale + mB;
            float newm = fmaxf(m[h], fmaxf(scA, scB));
            if (newm > m[h]) {          // warp-uniform branch
                float fac = __expf(m[h] - newm);
                lsum[h] *= fac;
                acc[h].x *= fac; acc[h].y *= fac; acc[h].z *= fac; acc[h].w *= fac;
                m[h] = newm;
            }
            float pA = __expf(scA - m[h]);
            float pB = __expf(scB - m[h]);
            lsum[h] += pA + pB;
            acc[h].x = fmaf(pA, vA.x, fmaf(pB, vB.x, acc[h].x));
            acc[h].y = fmaf(pA, vA.y, fmaf(pB, vB.y, acc[h].y));
            acc[h].z = fmaf(pA, vA.z, fmaf(pB, vB.z, acc[h].z));
            acc[h].w = fmaf(pA, vA.w, fmaf(pB, vB.w, acc[h].w));
        }
    }

#pragma unroll
    for (int h = 0; h < 4; h++)
        *(float4*)&sacc[w][h][4 * l] = acc[h];
    if (l == 0) {
#pragma unroll
        for (int h = 0; h < 4; h++) { smx[w][h] = m[h]; slx[w][h] = lsum[h]; }
    }
    __syncthreads();

    // ---- combine the 8 warp partials -> split partials ----
    size_t pbase = ((size_t)(b * NKV + kv) * SPLITS + sp) * 4;
    for (int o = tid; o < 4 * HD; o += 256) {
        int h = o / HD, d = o % HD;
        float M = -1e30f;
#pragma unroll
        for (int ww = 0; ww < 8; ww++) M = fmaxf(M, smx[ww][h]);
        float L = 0.f, s = 0.f;
#pragma unroll
        for (int ww = 0; ww < 8; ww++) {
            float fac = __expf(smx[ww][h] - M);
            s += sacc[ww][h][d] * fac;
            L += slx[ww][h] * fac;
        }
        g_pacc[(pbase + h) * HD + d] = s;
        if (d == 0) { g_pm[pbase + h] = M; g_pl[pbase + h] = L; }
    }
}

// ---------------- combine split partials ----------------
__global__ void combine_kernel() {
    int h = blockIdx.x, b = blockIdx.y, d = threadIdx.x;
    int kv = h >> 2, r = h & 3;
    size_t base = (size_t)(b * NKV + kv) * SPLITS;
    float M = -1e30f;
#pragma unroll
    for (int s = 0; s < SPLITS; s++) M = fmaxf(M, g_pm[(base + s) * 4 + r]);
    float L = 0.f, acc = 0.f;
#pragma unroll
    for (int s = 0; s < SPLITS; s++) {
        float wgt = __expf(g_pm[(base + s) * 4 + r] - M);
        L += g_pl[(base + s) * 4 + r] * wgt;
        acc += g_pacc[((base + s) * 4 + r) * HD + d] * wgt;
    }
    g_attn[b * (NH * HD) + h * HD + d] = acc / L;
}

// ---------------- reduce wo-GEMM partials -> final out ----------------
__global__ void reduce_out_kernel(float* __restrict__ out) {
    int i = blockIdx.x * 256 + threadIdx.x;
    float s = 0.f;
#pragma unroll
    for (int ks = 0; ks < KSPLIT; ks++) s += g_opart[ks][i];
    out[i] = s;
}

// ---------------- launch ----------------
extern "C" void kernel_launch(void* const* d_in, const int* in_sizes, int n_in,
                              void* d_out, int out_size) {
    const float* x       = (const float*)d_in[0];
    const float* mask    = (const float*)d_in[1];
    const float* rope    = (const float*)d_in[2];
    const float* wq      = (const float*)d_in[3];
    const float* wk      = (const float*)d_in[4];
    const float* wv      = (const float*)d_in[5];
    const float* wo      = (const float*)d_in[6];
    const float* cache_k = (const float*)d_in[7];
    const float* cache_v = (const float*)d_in[8];
    const int*   last_pos = (const int*)d_in[9];

    float* out   = (float*)d_out;
    float* out_k = out + (size_t)BS * HIDDEN;
    float* out_v = out_k + (size_t)BS * SEQ * NKV * HD;

    qkv_gemm_kernel<<<dim3(QKV_N / 128, KSPLIT), 128>>>(x, wq, wk, wv);
    rope_reduce_kernel<<<(BS * QKV_N / 2) / 256, 256>>>(rope, last_pos);
    attn_kernel<<<dim3(SPLITS, NKV, BS), 256>>>(cache_k, cache_v, mask, last_pos, out_k, out_v);
    combine_kernel<<<dim3(NH, BS), HD>>>();
    wo_gemm_kernel<<<dim3(HIDDEN / 128, KSPLIT), 128>>>(wo);
    reduce_out_kernel<<<(BS * HIDDEN) / 256, 256>>>(out);
}

// round 4
// speedup vs baseline: 1.7919x; 1.0550x over previous
#include <cuda_runtime.h>
#include <cstdint>

#define HIDDEN 4096
#define NH 32
#define NKV 8
#define HD 128
#define BS 16
#define SEQ 4096
#define QKV_N 6144           // 4096 q + 1024 k + 1024 v
#define KSPLIT 16
#define KC (HIDDEN / KSPLIT) // 256
#define SPLITS 32
#define CHUNK (SEQ / SPLITS) // 128

// ---------------- scratch (device globals; no allocs allowed) ----------------
__device__ float g_qkvpart[KSPLIT][BS * QKV_N];  // GEMM partials for q|k|v
__device__ float g_q[BS * NH * HD];              // rope'd q
__device__ float g_k[BS * NKV * HD];             // rope'd new k
__device__ float g_v[BS * NKV * HD];             // new v
__device__ float g_pacc[BS * NKV * SPLITS * 4 * HD]; // flash partial accumulators
__device__ float g_pm[BS * NKV * SPLITS * 4];        // partial max
__device__ float g_pl[BS * NKV * SPLITS * 4];        // partial sumexp
__device__ float g_attn[BS * NH * HD];           // attention output pre-wo
__device__ float g_opart[KSPLIT][BS * HIDDEN];   // wo GEMM partials

// ---------------- fused qkv skinny GEMM: [16 x 4096] @ [4096 x 6144] ----------------
__global__ void qkv_gemm_kernel(const float* __restrict__ X,
                                const float* __restrict__ wq,
                                const float* __restrict__ wk,
                                const float* __restrict__ wv) {
    __shared__ float xs[BS][KC];
    int ng = blockIdx.x * 128 + threadIdx.x;   // global col in [0, 6144)
    int k0 = blockIdx.y * KC;

    const float* W; int col, Nw;
    if (ng < NH * HD)              { W = wq; col = ng;            Nw = NH * HD; }
    else if (ng < (NH + NKV) * HD) { W = wk; col = ng - NH * HD;  Nw = NKV * HD; }
    else                           { W = wv; col = ng - (NH + NKV) * HD; Nw = NKV * HD; }

    for (int i = threadIdx.x; i < BS * KC; i += 128) {
        int b = i / KC, k = i % KC;
        xs[b][k] = X[b * HIDDEN + k0 + k];
    }
    __syncthreads();

    float acc[BS];
#pragma unroll
    for (int b = 0; b < BS; b++) acc[b] = 0.f;

    const float* Wp = W + (size_t)k0 * Nw + col;
    float w0 = Wp[0], w1 = Wp[(size_t)Nw], w2 = Wp[2 * (size_t)Nw], w3 = Wp[3 * (size_t)Nw];
#pragma unroll 1
    for (int k = 0; k < KC; k += 4) {
        float n0 = 0.f, n1 = 0.f, n2 = 0.f, n3 = 0.f;
        if (k + 4 < KC) {
            const float* Wn = Wp + (size_t)(k + 4) * Nw;
            n0 = Wn[0]; n1 = Wn[(size_t)Nw]; n2 = Wn[2 * (size_t)Nw]; n3 = Wn[3 * (size_t)Nw];
        }
#pragma unroll
        for (int b = 0; b < BS; b++) {
            acc[b] = fmaf(xs[b][k],     w0, acc[b]);
            acc[b] = fmaf(xs[b][k + 1], w1, acc[b]);
            acc[b] = fmaf(xs[b][k + 2], w2, acc[b]);
            acc[b] = fmaf(xs[b][k + 3], w3, acc[b]);
        }
        w0 = n0; w1 = n1; w2 = n2; w3 = n3;
    }

    size_t base = (size_t)blockIdx.y * BS * QKV_N;
#pragma unroll
    for (int b = 0; b < BS; b++)
        g_qkvpart[0][base + (size_t)b * QKV_N + ng] = acc[b];
}

// ---------------- wo skinny GEMM: g_attn [16 x 4096] @ wo [4096 x 4096] ----------------
__global__ void wo_gemm_kernel(const float* __restrict__ W) {
    __shared__ float xs[BS][KC];
    int n = blockIdx.x * 128 + threadIdx.x;
    int k0 = blockIdx.y * KC;

    for (int i = threadIdx.x; i < BS * KC; i += 128) {
        int b = i / KC, k = i % KC;
        xs[b][k] = g_attn[b * HIDDEN + k0 + k];
    }
    __syncthreads();

    float acc[BS];
#pragma unroll
    for (int b = 0; b < BS; b++) acc[b] = 0.f;

    const float* Wp = W + (size_t)k0 * HIDDEN + n;
    float w0 = Wp[0], w1 = Wp[HIDDEN], w2 = Wp[2 * HIDDEN], w3 = Wp[3 * HIDDEN];
#pragma unroll 1
    for (int k = 0; k < KC; k += 4) {
        float n0 = 0.f, n1 = 0.f, n2 = 0.f, n3 = 0.f;
        if (k + 4 < KC) {
            const float* Wn = Wp + (size_t)(k + 4) * HIDDEN;
            n0 = Wn[0]; n1 = Wn[HIDDEN]; n2 = Wn[2 * HIDDEN]; n3 = Wn[3 * HIDDEN];
        }
#pragma unroll
        for (int b = 0; b < BS; b++) {
            acc[b] = fmaf(xs[b][k],     w0, acc[b]);
            acc[b] = fmaf(xs[b][k + 1], w1, acc[b]);
            acc[b] = fmaf(xs[b][k + 2], w2, acc[b]);
            acc[b] = fmaf(xs[b][k + 3], w3, acc[b]);
        }
        w0 = n0; w1 = n1; w2 = n2; w3 = n3;
    }

    size_t base = (size_t)blockIdx.y * BS * HIDDEN;
#pragma unroll
    for (int b = 0; b < BS; b++)
        g_opart[0][base + (size_t)b * HIDDEN + n] = acc[b];
}

// ---------------- parallel reduce partials + RoPE + stage q/k/v ----------------
__global__ void rope_reduce_kernel(const float* __restrict__ rope_cache,
                                   const int* __restrict__ last_pos) {
    int idx = blockIdx.x * 256 + threadIdx.x;       // pair index
    int b = idx / (QKV_N / 2);
    int i = (idx % (QKV_N / 2)) * 2;

    float v0 = 0.f, v1 = 0.f;
#pragma unroll
    for (int ks = 0; ks < KSPLIT; ks++) {
        const float2 s = *(const float2*)&g_qkvpart[ks][b * QKV_N + i];
        v0 += s.x; v1 += s.y;
    }

    float o0 = v0, o1 = v1;
    if (i < (NH + NKV) * HD) {   // rope on q and k
        int lp = last_pos[b];
        int pi = (i % HD) >> 1;
        const float2 cs = *(const float2*)(rope_cache + (size_t)lp * HD + 2 * pi);
        o0 = v0 * cs.x - v1 * cs.y;
        o1 = v1 * cs.x + v0 * cs.y;
    }

    float* dst;
    if (i < NH * HD)                 dst = g_q + b * (NH * HD) + i;
    else if (i < (NH + NKV) * HD)    dst = g_k + b * (NKV * HD) + (i - NH * HD);
    else                             dst = g_v + b * (NKV * HD) + (i - (NH + NKV) * HD);
    dst[0] = o0;
    dst[1] = o1;
}

// ---------------- single-pass fused cache-copy + online-softmax flash decode ----------------
// grid (SPLITS, NKV, BS) = 4096 blocks, 256 threads (8 warps).
// Each warp streams 4 K rows + 4 V rows per iteration (8 independent LDG.128 in
// flight), maintains per-head online softmax state, then block-combines.
__global__ void __launch_bounds__(256, 2)
attn_kernel(const float* __restrict__ cache_k,
            const float* __restrict__ cache_v,
            const float* __restrict__ mask,
            const int* __restrict__ last_pos,
            float* __restrict__ out_k, float* __restrict__ out_v) {
    __shared__ float sq[4][HD];
    __shared__ float sacc[8][4][HD];   // per-warp V accumulators (16 KB)
    __shared__ float smx[8][4], slx[8][4];

    int sp = blockIdx.x, kv = blockIdx.y, b = blockIdx.z;
    int tid = threadIdx.x;
    int j0 = sp * CHUNK;
    int lp = last_pos[b];
    int w = tid >> 5, l = tid & 31;

    for (int i = tid; i < 4 * HD; i += 256) {
        int h = i / HD, d = i % HD;
        sq[h][d] = g_q[b * (NH * HD) + (kv * 4 + h) * HD + d];
    }
    __syncthreads();

    float4 qr[4];
#pragma unroll
    for (int h = 0; h < 4; h++) qr[h] = *(float4*)&sq[h][4 * l];

    const float scale = 0.08838834764831845f; // 1/sqrt(128)
    const float4* newk = (const float4*)(g_k + (b * NKV + kv) * HD);
    const float4* newv = (const float4*)(g_v + (b * NKV + kv) * HD);

    float4 acc[4];
    float m[4], lsum[4];
#pragma unroll
    for (int h = 0; h < 4; h++) {
        acc[h] = make_float4(0.f, 0.f, 0.f, 0.f);
        m[h] = -1e30f;
        lsum[h] = 0.f;
    }

#pragma unroll 1
    for (int it = 0; it < CHUNK / 32; it++) {
        int jb = j0 + it * 32 + w * 4;             // 4 consecutive rows per warp
        size_t row0 = ((size_t)(b * SEQ + jb) * NKV + kv) * HD;

        float4 kR[4], vR[4];
#pragma unroll
        for (int r = 0; r < 4; r++) {
            const float4* kp = (jb + r == lp) ? newk
                             : (const float4*)(cache_k + row0 + (size_t)r * (NKV * HD));
            kR[r] = __ldcs(kp + l);
        }
#pragma unroll
        for (int r = 0; r < 4; r++) {
            const float4* vp = (jb + r == lp) ? newv
                             : (const float4*)(cache_v + row0 + (size_t)r * (NKV * HD));
            vR[r] = __ldcs(vp + l);
        }
#pragma unroll
        for (int r = 0; r < 4; r++) {
            size_t row = row0 + (size_t)r * (NKV * HD);
            __stcs((float4*)(out_k + row) + l, kR[r]);
            __stcs((float4*)(out_v + row) + l, vR[r]);
        }

        float s[4][4];
#pragma unroll
        for (int r = 0; r < 4; r++)
#pragma unroll
            for (int h = 0; h < 4; h++)
                s[r][h] = qr[h].x * kR[r].x + qr[h].y * kR[r].y
                        + qr[h].z * kR[r].z + qr[h].w * kR[r].w;
#pragma unroll
        for (int off = 16; off; off >>= 1)
#pragma unroll
            for (int r = 0; r < 4; r++)
#pragma unroll
                for (int h = 0; h < 4; h++)
                    s[r][h] += __shfl_xor_sync(0xffffffffu, s[r][h], off);

        float4 mq = __ldg((const float4*)(mask + b * SEQ + jb));  // jb % 4 == 0
        float mk[4] = {mq.x, mq.y, mq.z, mq.w};

#pragma unroll
        for (int h = 0; h < 4; h++) {
            float sc0 = s[0][h] * scale + mk[0];
            float sc1 = s[1][h] * scale + mk[1];
            float sc2 = s[2][h] * scale + mk[2];
            float sc3 = s[3][h] * scale + mk[3];
            float newm = fmaxf(fmaxf(sc0, sc1), fmaxf(sc2, sc3));
            newm = fmaxf(newm, m[h]);
            if (newm > m[h]) {          // warp-uniform branch
                float fac = __expf(m[h] - newm);
                lsum[h] *= fac;
                acc[h].x *= fac; acc[h].y *= fac; acc[h].z *= fac; acc[h].w *= fac;
                m[h] = newm;
            }
            float p0 = __expf(sc0 - m[h]);
            float p1 = __expf(sc1 - m[h]);
            float p2 = __expf(sc2 - m[h]);
            float p3 = __expf(sc3 - m[h]);
            lsum[h] += (p0 + p1) + (p2 + p3);
            acc[h].x = fmaf(p0, vR[0].x, fmaf(p1, vR[1].x, fmaf(p2, vR[2].x, fmaf(p3, vR[3].x, acc[h].x))));
            acc[h].y = fmaf(p0, vR[0].y, fmaf(p1, vR[1].y, fmaf(p2, vR[2].y, fmaf(p3, vR[3].y, acc[h].y))));
            acc[h].z = fmaf(p0, vR[0].z, fmaf(p1, vR[1].z, fmaf(p2, vR[2].z, fmaf(p3, vR[3].z, acc[h].z))));
            acc[h].w = fmaf(p0, vR[0].w, fmaf(p1, vR[1].w, fmaf(p2, vR[2].w, fmaf(p3, vR[3].w, acc[h].w))));
        }
    }

#pragma unroll
    for (int h = 0; h < 4; h++)
        *(float4*)&sacc[w][h][4 * l] = acc[h];
    if (l == 0) {
#pragma unroll
        for (int h = 0; h < 4; h++) { smx[w][h] = m[h]; slx[w][h] = lsum[h]; }
    }
    __syncthreads();

    // ---- combine the 8 warp partials -> split partials ----
    size_t pbase = ((size_t)(b * NKV + kv) * SPLITS + sp) * 4;
    for (int o = tid; o < 4 * HD; o += 256) {
        int h = o / HD, d = o % HD;
        float M = -1e30f;
#pragma unroll
        for (int ww = 0; ww < 8; ww++) M = fmaxf(M, smx[ww][h]);
        float L = 0.f, s = 0.f;
#pragma unroll
        for (int ww = 0; ww < 8; ww++) {
            float fac = __expf(smx[ww][h] - M);
            s += sacc[ww][h][d] * fac;
            L += slx[ww][h] * fac;
        }
        g_pacc[(pbase + h) * HD + d] = s;
        if (d == 0) { g_pm[pbase + h] = M; g_pl[pbase + h] = L; }
    }
}

// ---------------- combine split partials ----------------
// grid (NH, BS), one warp per block; lane l owns float4 at d = 4*l.
__global__ void combine_kernel() {
    int h = blockIdx.x, b = blockIdx.y, l = threadIdx.x;
    int kv = h >> 2, r = h & 3;
    size_t base = (size_t)(b * NKV + kv) * SPLITS;
    float M = -1e30f;
#pragma unroll
    for (int s = 0; s < SPLITS; s++) M = fmaxf(M, g_pm[(base + s) * 4 + r]);
    float L = 0.f;
    float4 acc = make_float4(0.f, 0.f, 0.f, 0.f);
#pragma unroll
    for (int s = 0; s < SPLITS; s++) {
        float wgt = __expf(g_pm[(base + s) * 4 + r] - M);
        L += g_pl[(base + s) * 4 + r] * wgt;
        float4 p = *(const float4*)&g_pacc[((base + s) * 4 + r) * HD + 4 * l];
        acc.x = fmaf(p.x, wgt, acc.x);
        acc.y = fmaf(p.y, wgt, acc.y);
        acc.z = fmaf(p.z, wgt, acc.z);
        acc.w = fmaf(p.w, wgt, acc.w);
    }
    float inv = 1.f / L;
    acc.x *= inv; acc.y *= inv; acc.z *= inv; acc.w *= inv;
    *(float4*)&g_attn[b * (NH * HD) + h * HD + 4 * l] = acc;
}

// ---------------- reduce wo-GEMM partials -> final out ----------------
__global__ void reduce_out_kernel(float* __restrict__ out) {
    int i = (blockIdx.x * 256 + threadIdx.x) * 4;
    float4 s = make_float4(0.f, 0.f, 0.f, 0.f);
#pragma unroll
    for (int ks = 0; ks < KSPLIT; ks++) {
        float4 p = *(const float4*)&g_opart[ks][i];
        s.x += p.x; s.y += p.y; s.z += p.z; s.w += p.w;
    }
    *(float4*)(out + i) = s;
}

// ---------------- launch ----------------
extern "C" void kernel_launch(void* const* d_in, const int* in_sizes, int n_in,
                              void* d_out, int out_size) {
    const float* x       = (const float*)d_in[0];
    const float* mask    = (const float*)d_in[1];
    const float* rope    = (const float*)d_in[2];
    const float* wq      = (const float*)d_in[3];
    const float* wk      = (const float*)d_in[4];
    const float* wv      = (const float*)d_in[5];
    const float* wo      = (const float*)d_in[6];
    const float* cache_k = (const float*)d_in[7];
    const float* cache_v = (const float*)d_in[8];
    const int*   last_pos = (const int*)d_in[9];

    float* out   = (float*)d_out;
    float* out_k = out + (size_t)BS * HIDDEN;
    float* out_v = out_k + (size_t)BS * SEQ * NKV * HD;

    qkv_gemm_kernel<<<dim3(QKV_N / 128, KSPLIT), 128>>>(x, wq, wk, wv);
    rope_reduce_kernel<<<(BS * QKV_N / 2) / 256, 256>>>(rope, last_pos);
    attn_kernel<<<dim3(SPLITS, NKV, BS), 256>>>(cache_k, cache_v, mask, last_pos, out_k, out_v);
    combine_kernel<<<dim3(NH, BS), 32>>>();
    wo_gemm_kernel<<<dim3(HIDDEN / 128, KSPLIT), 128>>>(wo);
    reduce_out_kernel<<<(BS * HIDDEN / 4) / 256, 256>>>(out);
}

// round 5
// speedup vs baseline: 1.9353x; 1.0801x over previous
#include <cuda_runtime.h>
#include <cstdint>

#define HIDDEN 4096
#define NH 32
#define NKV 8
#define HD 128
#define BS 16
#define SEQ 4096
#define QKV_N 6144           // 4096 q + 1024 k + 1024 v
#define KSPLIT 16
#define KC (HIDDEN / KSPLIT) // 256
#define SPLITS 32
#define CHUNK (SEQ / SPLITS) // 128
#define TILE 16
#define NT (CHUNK / TILE)    // 8

// ---------------- scratch (device globals; no allocs allowed) ----------------
__device__ float g_qkvpart[KSPLIT][BS * QKV_N];  // GEMM partials for q|k|v
__device__ float g_q[BS * NH * HD];              // rope'd q
__device__ float g_k[BS * NKV * HD];             // rope'd new k
__device__ float g_v[BS * NKV * HD];             // new v
__device__ float g_pacc[BS * NKV * SPLITS * 4 * HD]; // flash partial accumulators
__device__ float g_pm[BS * NKV * SPLITS * 4];        // partial max
__device__ float g_pl[BS * NKV * SPLITS * 4];        // partial sumexp
__device__ float g_attn[BS * NH * HD];           // attention output pre-wo
__device__ float g_opart[KSPLIT][BS * HIDDEN];   // wo GEMM partials

__device__ __forceinline__ void cp16(void* smem_dst, const void* gsrc) {
    uint32_t s = (uint32_t)__cvta_generic_to_shared(smem_dst);
    asm volatile("cp.async.cg.shared.global [%0], [%1], 16;" :: "r"(s), "l"(gsrc));
}

// ---------------- fused qkv skinny GEMM: [16 x 4096] @ [4096 x 6144] ----------------
__global__ void qkv_gemm_kernel(const float* __restrict__ X,
                                const float* __restrict__ wq,
                                const float* __restrict__ wk,
                                const float* __restrict__ wv) {
    __shared__ float xs[BS][KC];
    int ng = blockIdx.x * 128 + threadIdx.x;   // global col in [0, 6144)
    int k0 = blockIdx.y * KC;

    const float* W; int col, Nw;
    if (ng < NH * HD)              { W = wq; col = ng;            Nw = NH * HD; }
    else if (ng < (NH + NKV) * HD) { W = wk; col = ng - NH * HD;  Nw = NKV * HD; }
    else                           { W = wv; col = ng - (NH + NKV) * HD; Nw = NKV * HD; }

    for (int i = threadIdx.x; i < BS * KC; i += 128) {
        int b = i / KC, k = i % KC;
        xs[b][k] = X[b * HIDDEN + k0 + k];
    }
    __syncthreads();

    float acc[BS];
#pragma unroll
    for (int b = 0; b < BS; b++) acc[b] = 0.f;

    const float* Wp = W + (size_t)k0 * Nw + col;
    float wb[8];
#pragma unroll
    for (int i = 0; i < 8; i++) wb[i] = __ldcs(Wp + (size_t)i * Nw);
#pragma unroll 1
    for (int k = 0; k < KC; k += 8) {
        float nb[8];
        if (k + 8 < KC) {
            const float* Wn = Wp + (size_t)(k + 8) * Nw;
#pragma unroll
            for (int i = 0; i < 8; i++) nb[i] = __ldcs(Wn + (size_t)i * Nw);
        } else {
#pragma unroll
            for (int i = 0; i < 8; i++) nb[i] = 0.f;
        }
#pragma unroll
        for (int i = 0; i < 8; i++)
#pragma unroll
            for (int b = 0; b < BS; b++)
                acc[b] = fmaf(xs[b][k + i], wb[i], acc[b]);
#pragma unroll
        for (int i = 0; i < 8; i++) wb[i] = nb[i];
    }

    size_t base = (size_t)blockIdx.y * BS * QKV_N;
#pragma unroll
    for (int b = 0; b < BS; b++)
        g_qkvpart[0][base + (size_t)b * QKV_N + ng] = acc[b];
}

// ---------------- wo skinny GEMM: g_attn [16 x 4096] @ wo [4096 x 4096] ----------------
__global__ void wo_gemm_kernel(const float* __restrict__ W) {
    __shared__ float xs[BS][KC];
    int n = blockIdx.x * 128 + threadIdx.x;
    int k0 = blockIdx.y * KC;

    for (int i = threadIdx.x; i < BS * KC; i += 128) {
        int b = i / KC, k = i % KC;
        xs[b][k] = g_attn[b * HIDDEN + k0 + k];
    }
    __syncthreads();

    float acc[BS];
#pragma unroll
    for (int b = 0; b < BS; b++) acc[b] = 0.f;

    const float* Wp = W + (size_t)k0 * HIDDEN + n;
    float wb[8];
#pragma unroll
    for (int i = 0; i < 8; i++) wb[i] = __ldcs(Wp + (size_t)i * HIDDEN);
#pragma unroll 1
    for (int k = 0; k < KC; k += 8) {
        float nb[8];
        if (k + 8 < KC) {
            const float* Wn = Wp + (size_t)(k + 8) * HIDDEN;
#pragma unroll
            for (int i = 0; i < 8; i++) nb[i] = __ldcs(Wn + (size_t)i * HIDDEN);
        } else {
#pragma unroll
            for (int i = 0; i < 8; i++) nb[i] = 0.f;
        }
#pragma unroll
        for (int i = 0; i < 8; i++)
#pragma unroll
            for (int b = 0; b < BS; b++)
                acc[b] = fmaf(xs[b][k + i], wb[i], acc[b]);
#pragma unroll
        for (int i = 0; i < 8; i++) wb[i] = nb[i];
    }

    size_t base = (size_t)blockIdx.y * BS * HIDDEN;
#pragma unroll
    for (int b = 0; b < BS; b++)
        g_opart[0][base + (size_t)b * HIDDEN + n] = acc[b];
}

// ---------------- parallel reduce partials + RoPE + stage q/k/v ----------------
__global__ void rope_reduce_kernel(const float* __restrict__ rope_cache,
                                   const int* __restrict__ last_pos) {
    int idx = blockIdx.x * 256 + threadIdx.x;       // pair index
    int b = idx / (QKV_N / 2);
    int i = (idx % (QKV_N / 2)) * 2;

    float v0 = 0.f, v1 = 0.f;
#pragma unroll
    for (int ks = 0; ks < KSPLIT; ks++) {
        const float2 s = *(const float2*)&g_qkvpart[ks][b * QKV_N + i];
        v0 += s.x; v1 += s.y;
    }

    float o0 = v0, o1 = v1;
    if (i < (NH + NKV) * HD) {   // rope on q and k
        int lp = last_pos[b];
        int pi = (i % HD) >> 1;
        const float2 cs = *(const float2*)(rope_cache + (size_t)lp * HD + 2 * pi);
        o0 = v0 * cs.x - v1 * cs.y;
        o1 = v1 * cs.x + v0 * cs.y;
    }

    float* dst;
    if (i < NH * HD)                 dst = g_q + b * (NH * HD) + i;
    else if (i < (NH + NKV) * HD)    dst = g_k + b * (NKV * HD) + (i - NH * HD);
    else                             dst = g_v + b * (NKV * HD) + (i - (NH + NKV) * HD);
    dst[0] = o0;
    dst[1] = o1;
}

// ---------------- cp.async-pipelined fused cache-copy + online-softmax decode ----------------
// grid (SPLITS, NKV, BS) = 4096 blocks, 256 threads (8 warps).
// Double-buffered 16-row K/V tiles streamed via cp.async (no registers held across
// DRAM latency); compute + copy-out read the arrived smem tile.
__global__ void __launch_bounds__(256, 2)
attn_kernel(const float* __restrict__ cache_k,
            const float* __restrict__ cache_v,
            const float* __restrict__ mask,
            const int* __restrict__ last_pos,
            float* __restrict__ out_k, float* __restrict__ out_v) {
    __shared__ float sq[4][HD];                    // 2 KB
    __shared__ float4 kbuf[2][TILE][HD / 4];       // 16 KB
    __shared__ float4 vbuf[2][TILE][HD / 4];       // 16 KB
    __shared__ float smx[8][4], slx[8][4];

    int sp = blockIdx.x, kv = blockIdx.y, b = blockIdx.z;
    int tid = threadIdx.x;
    int j0 = sp * CHUNK;
    int lp = last_pos[b];
    int w = tid >> 5, l = tid & 31;

    for (int i = tid; i < 4 * HD; i += 256) {
        int h = i / HD, d = i % HD;
        sq[h][d] = g_q[b * (NH * HD) + (kv * 4 + h) * HD + d];
    }

    const float* newk = g_k + (b * NKV + kv) * HD;
    const float* newv = g_v + (b * NKV + kv) * HD;
    const size_t cbase = ((size_t)b * SEQ) * (NKV * HD) + (size_t)kv * HD;
    const int c0 = tid >> 5, off0 = tid & 31;      // chunk decomposition: c = tid + 256*i

    // --- tile loader: 16 rows x 512B of K and V via cp.async (2+2 per thread) ---
    auto load_tile = [&](int t, int buf) {
#pragma unroll
        for (int i = 0; i < 2; i++) {
            int rr = c0 + 8 * i, off = off0;
            int j = j0 + t * TILE + rr;
            const float* ks = (j == lp) ? (newk + off * 4)
                            : (cache_k + cbase + (size_t)j * (NKV * HD) + off * 4);
            cp16(&kbuf[buf][rr][off], ks);
        }
#pragma unroll
        for (int i = 0; i < 2; i++) {
            int rr = c0 + 8 * i, off = off0;
            int j = j0 + t * TILE + rr;
            const float* vs = (j == lp) ? (newv + off * 4)
                            : (cache_v + cbase + (size_t)j * (NKV * HD) + off * 4);
            cp16(&vbuf[buf][rr][off], vs);
        }
        asm volatile("cp.async.commit_group;");
    };

    load_tile(0, 0);
    load_tile(1, 1);
    __syncthreads();   // sq visible; pipeline primed

    float4 qr[4];
#pragma unroll
    for (int h = 0; h < 4; h++) qr[h] = *(float4*)&sq[h][4 * l];

    const float scale = 0.08838834764831845f; // 1/sqrt(128)
    float4 acc[4];
    float m[4], lsum[4];
#pragma unroll
    for (int h = 0; h < 4; h++) {
        acc[h] = make_float4(0.f, 0.f, 0.f, 0.f);
        m[h] = -1e30f;
        lsum[h] = 0.f;
    }

    const int rloc = w * 2;                        // this warp's 2 rows within tile
#pragma unroll 1
    for (int t = 0; t < NT; t++) {
        if (t < NT - 1) asm volatile("cp.async.wait_group 1;");
        else            asm volatile("cp.async.wait_group 0;");
        __syncthreads();

        int buf = t & 1;
        int jb = j0 + t * TILE + rloc;
        float4 k0r = kbuf[buf][rloc][l];
        float4 k1r = kbuf[buf][rloc + 1][l];
        float4 v0r = vbuf[buf][rloc][l];
        float4 v1r = vbuf[buf][rloc + 1][l];

        size_t row0 = cbase + (size_t)jb * (NKV * HD);
        __stcs((float4*)(out_k + row0) + l, k0r);
        __stcs((float4*)(out_k + row0 + (size_t)(NKV * HD)) + l, k1r);
        __stcs((float4*)(out_v + row0) + l, v0r);
        __stcs((float4*)(out_v + row0 + (size_t)(NKV * HD)) + l, v1r);

        float s0[4], s1[4];
#pragma unroll
        for (int h = 0; h < 4; h++) {
            s0[h] = qr[h].x * k0r.x + qr[h].y * k0r.y + qr[h].z * k0r.z + qr[h].w * k0r.w;
            s1[h] = qr[h].x * k1r.x + qr[h].y * k1r.y + qr[h].z * k1r.z + qr[h].w * k1r.w;
        }
#pragma unroll
        for (int offx = 16; offx; offx >>= 1) {
#pragma unroll
            for (int h = 0; h < 4; h++) {
                s0[h] += __shfl_xor_sync(0xffffffffu, s0[h], offx);
                s1[h] += __shfl_xor_sync(0xffffffffu, s1[h], offx);
            }
        }

        float2 mq = __ldg((const float2*)(mask + b * SEQ + jb));

#pragma unroll
        for (int h = 0; h < 4; h++) {
            float sc0 = s0[h] * scale + mq.x;
            float sc1 = s1[h] * scale + mq.y;
            float newm = fmaxf(m[h], fmaxf(sc0, sc1));
            if (newm > m[h]) {                    // warp-uniform branch
                float fac = __expf(m[h] - newm);
                lsum[h] *= fac;
                acc[h].x *= fac; acc[h].y *= fac; acc[h].z *= fac; acc[h].w *= fac;
                m[h] = newm;
            }
            float p0 = __expf(sc0 - m[h]);
            float p1 = __expf(sc1 - m[h]);
            lsum[h] += p0 + p1;
            acc[h].x = fmaf(p0, v0r.x, fmaf(p1, v1r.x, acc[h].x));
            acc[h].y = fmaf(p0, v0r.y, fmaf(p1, v1r.y, acc[h].y));
            acc[h].z = fmaf(p0, v0r.z, fmaf(p1, v1r.z, acc[h].z));
            acc[h].w = fmaf(p0, v0r.w, fmaf(p1, v1r.w, acc[h].w));
        }

        __syncthreads();                          // tile consumed; safe to refill buf
        if (t + 2 < NT) load_tile(t + 2, buf);
    }

    // ---- combine the 8 warp partials (sacc aliases the kbuf region) ----
    float* sacc = (float*)&kbuf[0][0][0];         // 8*4*128 floats = 16 KB
#pragma unroll
    for (int h = 0; h < 4; h++)
        *(float4*)&sacc[(w * 4 + h) * HD + 4 * l] = acc[h];
    if (l == 0) {
#pragma unroll
        for (int h = 0; h < 4; h++) { smx[w][h] = m[h]; slx[w][h] = lsum[h]; }
    }
    __syncthreads();

    size_t pbase = ((size_t)(b * NKV + kv) * SPLITS + sp) * 4;
    for (int o = tid; o < 4 * HD; o += 256) {
        int h = o / HD, d = o % HD;
        float M = -1e30f;
#pragma unroll
        for (int ww = 0; ww < 8; ww++) M = fmaxf(M, smx[ww][h]);
        float L = 0.f, s = 0.f;
#pragma unroll
        for (int ww = 0; ww < 8; ww++) {
            float fac = __expf(smx[ww][h] - M);
            s += sacc[(ww * 4 + h) * HD + d] * fac;
            L += slx[ww][h] * fac;
        }
        g_pacc[(pbase + h) * HD + d] = s;
        if (d == 0) { g_pm[pbase + h] = M; g_pl[pbase + h] = L; }
    }
}

// ---------------- combine split partials ----------------
// grid (BS*NKV), 128 threads: (r = head-in-group, l = float4 lane of HD)
__global__ void combine_kernel() {
    int bk = blockIdx.x;
    int r = threadIdx.x >> 5, l = threadIdx.x & 31;
    size_t base = (size_t)bk * SPLITS;

    float M = -1e30f;
#pragma unroll
    for (int s = 0; s < SPLITS; s++) M = fmaxf(M, g_pm[(base + s) * 4 + r]);
    float L = 0.f;
    float4 acc = make_float4(0.f, 0.f, 0.f, 0.f);
#pragma unroll
    for (int s = 0; s < SPLITS; s++) {
        float wgt = __expf(g_pm[(base + s) * 4 + r] - M);
        L += g_pl[(base + s) * 4 + r] * wgt;
        float4 p = *(const float4*)&g_pacc[((base + s) * 4 + r) * HD + 4 * l];
        acc.x = fmaf(p.x, wgt, acc.x);
        acc.y = fmaf(p.y, wgt, acc.y);
        acc.z = fmaf(p.z, wgt, acc.z);
        acc.w = fmaf(p.w, wgt, acc.w);
    }
    float inv = 1.f / L;
    acc.x *= inv; acc.y *= inv; acc.z *= inv; acc.w *= inv;
    int b = bk / NKV, kv = bk % NKV;
    *(float4*)&g_attn[b * (NH * HD) + (kv * 4 + r) * HD + 4 * l] = acc;
}

// ---------------- reduce wo-GEMM partials -> final out ----------------
__global__ void reduce_out_kernel(float* __restrict__ out) {
    int i = (blockIdx.x * 256 + threadIdx.x) * 4;
    float4 s = make_float4(0.f, 0.f, 0.f, 0.f);
#pragma unroll
    for (int ks = 0; ks < KSPLIT; ks++) {
        float4 p = *(const float4*)&g_opart[ks][i];
        s.x += p.x; s.y += p.y; s.z += p.z; s.w += p.w;
    }
    *(float4*)(out + i) = s;
}

// ---------------- launch ----------------
extern "C" void kernel_launch(void* const* d_in, const int* in_sizes, int n_in,
                              void* d_out, int out_size) {
    const float* x       = (const float*)d_in[0];
    const float* mask    = (const float*)d_in[1];
    const float* rope    = (const float*)d_in[2];
    const float* wq      = (const float*)d_in[3];
    const float* wk      = (const float*)d_in[4];
    const float* wv      = (const float*)d_in[5];
    const float* wo      = (const float*)d_in[6];
    const float* cache_k = (const float*)d_in[7];
    const float* cache_v = (const float*)d_in[8];
    const int*   last_pos = (const int*)d_in[9];

    float* out   = (float*)d_out;
    float* out_k = out + (size_t)BS * HIDDEN;
    float* out_v = out_k + (size_t)BS * SEQ * NKV * HD;

    qkv_gemm_kernel<<<dim3(QKV_N / 128, KSPLIT), 128>>>(x, wq, wk, wv);
    rope_reduce_kernel<<<(BS * QKV_N / 2) / 256, 256>>>(rope, last_pos);
    attn_kernel<<<dim3(SPLITS, NKV, BS), 256>>>(cache_k, cache_v, mask, last_pos, out_k, out_v);
    combine_kernel<<<BS * NKV, 128>>>();
    wo_gemm_kernel<<<dim3(HIDDEN / 128, KSPLIT), 128>>>(wo);
    reduce_out_kernel<<<(BS * HIDDEN / 4) / 256, 256>>>(out);
}

// round 6
// speedup vs baseline: 2.2733x; 1.1746x over previous
#include <cuda_runtime.h>
#include <cstdint>

#define HIDDEN 4096
#define NH 32
#define NKV 8
#define HD 128
#define BS 16
#define SEQ 4096
#define QKV_N 6144           // 4096 q + 1024 k + 1024 v
#define KSPLIT 16
#define KC (HIDDEN / KSPLIT) // 256
#define SPLITS 32
#define CHUNK (SEQ / SPLITS) // 128
#define WROWS 16             // rows per warp within chunk
#define NSTAGE 8             // WROWS / 2
#define DEPTH 4              // per-warp ring buffer depth (stages)

// ---------------- scratch (device globals; no allocs allowed) ----------------
__device__ float g_qkvpart[KSPLIT][BS * QKV_N];  // GEMM partials for q|k|v
__device__ float g_q[BS * NH * HD];              // rope'd q
__device__ float g_k[BS * NKV * HD];             // rope'd new k
__device__ float g_v[BS * NKV * HD];             // new v
__device__ float g_pacc[BS * NKV * SPLITS * 4 * HD]; // flash partial accumulators
__device__ float g_pm[BS * NKV * 4 * SPLITS];        // partial max  [head][split]
__device__ float g_pl[BS * NKV * 4 * SPLITS];        // partial sum  [head][split]
__device__ float g_attn[BS * NH * HD];           // attention output pre-wo
__device__ float g_opart[KSPLIT][BS * HIDDEN];   // wo GEMM partials

__device__ __forceinline__ void cp16(void* smem_dst, const void* gsrc) {
    uint32_t s = (uint32_t)__cvta_generic_to_shared(smem_dst);
    asm volatile("cp.async.cg.shared.global [%0], [%1], 16;" :: "r"(s), "l"(gsrc));
}

// ---------------- fused qkv skinny GEMM: [16 x 4096] @ [4096 x 6144] ----------------
__global__ void qkv_gemm_kernel(const float* __restrict__ X,
                                const float* __restrict__ wq,
                                const float* __restrict__ wk,
                                const float* __restrict__ wv) {
    __shared__ float xs[BS][KC];
    int ng = blockIdx.x * 128 + threadIdx.x;   // global col in [0, 6144)
    int k0 = blockIdx.y * KC;

    const float* W; int col, Nw;
    if (ng < NH * HD)              { W = wq; col = ng;            Nw = NH * HD; }
    else if (ng < (NH + NKV) * HD) { W = wk; col = ng - NH * HD;  Nw = NKV * HD; }
    else                           { W = wv; col = ng - (NH + NKV) * HD; Nw = NKV * HD; }

    for (int i = threadIdx.x; i < BS * KC; i += 128) {
        int b = i / KC, k = i % KC;
        xs[b][k] = X[b * HIDDEN + k0 + k];
    }
    __syncthreads();

    float acc[BS];
#pragma unroll
    for (int b = 0; b < BS; b++) acc[b] = 0.f;

    const float* Wp = W + (size_t)k0 * Nw + col;
    float wb[8];
#pragma unroll
    for (int i = 0; i < 8; i++) wb[i] = __ldcs(Wp + (size_t)i * Nw);
#pragma unroll 1
    for (int k = 0; k < KC; k += 8) {
        float nb[8];
        if (k + 8 < KC) {
            const float* Wn = Wp + (size_t)(k + 8) * Nw;
#pragma unroll
            for (int i = 0; i < 8; i++) nb[i] = __ldcs(Wn + (size_t)i * Nw);
        } else {
#pragma unroll
            for (int i = 0; i < 8; i++) nb[i] = 0.f;
        }
#pragma unroll
        for (int i = 0; i < 8; i++)
#pragma unroll
            for (int b = 0; b < BS; b++)
                acc[b] = fmaf(xs[b][k + i], wb[i], acc[b]);
#pragma unroll
        for (int i = 0; i < 8; i++) wb[i] = nb[i];
    }

    size_t base = (size_t)blockIdx.y * BS * QKV_N;
#pragma unroll
    for (int b = 0; b < BS; b++)
        g_qkvpart[0][base + (size_t)b * QKV_N + ng] = acc[b];
}

// ---------------- wo skinny GEMM: g_attn [16 x 4096] @ wo [4096 x 4096] ----------------
__global__ void wo_gemm_kernel(const float* __restrict__ W) {
    __shared__ float xs[BS][KC];
    int n = blockIdx.x * 128 + threadIdx.x;
    int k0 = blockIdx.y * KC;

    for (int i = threadIdx.x; i < BS * KC; i += 128) {
        int b = i / KC, k = i % KC;
        xs[b][k] = g_attn[b * HIDDEN + k0 + k];
    }
    __syncthreads();

    float acc[BS];
#pragma unroll
    for (int b = 0; b < BS; b++) acc[b] = 0.f;

    const float* Wp = W + (size_t)k0 * HIDDEN + n;
    float wb[8];
#pragma unroll
    for (int i = 0; i < 8; i++) wb[i] = __ldcs(Wp + (size_t)i * HIDDEN);
#pragma unroll 1
    for (int k = 0; k < KC; k += 8) {
        float nb[8];
        if (k + 8 < KC) {
            const float* Wn = Wp + (size_t)(k + 8) * HIDDEN;
#pragma unroll
            for (int i = 0; i < 8; i++) nb[i] = __ldcs(Wn + (size_t)i * HIDDEN);
        } else {
#pragma unroll
            for (int i = 0; i < 8; i++) nb[i] = 0.f;
        }
#pragma unroll
        for (int i = 0; i < 8; i++)
#pragma unroll
            for (int b = 0; b < BS; b++)
                acc[b] = fmaf(xs[b][k + i], wb[i], acc[b]);
#pragma unroll
        for (int i = 0; i < 8; i++) wb[i] = nb[i];
    }

    size_t base = (size_t)blockIdx.y * BS * HIDDEN;
#pragma unroll
    for (int b = 0; b < BS; b++)
        g_opart[0][base + (size_t)b * HIDDEN + n] = acc[b];
}

// ---------------- parallel reduce partials + RoPE + stage q/k/v ----------------
__global__ void rope_reduce_kernel(const float* __restrict__ rope_cache,
                                   const int* __restrict__ last_pos) {
    int idx = blockIdx.x * 256 + threadIdx.x;       // pair index
    int b = idx / (QKV_N / 2);
    int i = (idx % (QKV_N / 2)) * 2;

    float v0 = 0.f, v1 = 0.f;
#pragma unroll
    for (int ks = 0; ks < KSPLIT; ks++) {
        const float2 s = *(const float2*)&g_qkvpart[ks][b * QKV_N + i];
        v0 += s.x; v1 += s.y;
    }

    float o0 = v0, o1 = v1;
    if (i < (NH + NKV) * HD) {   // rope on q and k
        int lp = last_pos[b];
        int pi = (i % HD) >> 1;
        const float2 cs = *(const float2*)(rope_cache + (size_t)lp * HD + 2 * pi);
        o0 = v0 * cs.x - v1 * cs.y;
        o1 = v1 * cs.x + v0 * cs.y;
    }

    float* dst;
    if (i < NH * HD)                 dst = g_q + b * (NH * HD) + i;
    else if (i < (NH + NKV) * HD)    dst = g_k + b * (NKV * HD) + (i - NH * HD);
    else                             dst = g_v + b * (NKV * HD) + (i - (NH + NKV) * HD);
    dst[0] = o0;
    dst[1] = o1;
}

// ---------------- per-warp-pipelined fused cache-copy + online-softmax decode ----------------
// grid (SPLITS, NKV, BS) = 4096 blocks, 256 threads (8 warps).
// Each warp owns 16 contiguous rows of its 128-row chunk and runs a private
// 4-deep cp.async ring (2 rows K + 2 rows V per stage). Lane l loads & reads
// only column l -> no smem cross-thread visibility needed -> no __syncthreads
// in the main loop.
__global__ void __launch_bounds__(256)
attn_kernel(const float* __restrict__ cache_k,
            const float* __restrict__ cache_v,
            const float* __restrict__ mask,
            const int* __restrict__ last_pos,
            float* __restrict__ out_k, float* __restrict__ out_v) {
    extern __shared__ float4 dsm[];
    // layout: kb [8 warps][DEPTH][2 rows][32 lanes] float4 (32 KB)
    //         vb same (32 KB), sq 512 floats (2 KB)
    float4* kb = dsm;
    float4* vb = dsm + 8 * DEPTH * 2 * 32;
    float*  sq = (float*)(dsm + 2 * 8 * DEPTH * 2 * 32);
    __shared__ float smx[8][4], slx[8][4];

    int sp = blockIdx.x, kv = blockIdx.y, b = blockIdx.z;
    int tid = threadIdx.x;
    int j0 = sp * CHUNK;
    int lp = last_pos[b];
    int w = tid >> 5, l = tid & 31;

    const float* newk = g_k + (b * NKV + kv) * HD;
    const float* newv = g_v + (b * NKV + kv) * HD;
    const size_t cbase = ((size_t)b * SEQ) * (NKV * HD) + (size_t)kv * HD;
    const int jw = j0 + w * WROWS;                 // this warp's first row

    float4* kbw = kb + (size_t)w * (DEPTH * 2 * 32);
    float4* vbw = vb + (size_t)w * (DEPTH * 2 * 32);

    // per-warp stage loader: lane l loads column l of 2 K rows + 2 V rows
    auto load_stage = [&](int st) {
        int buf = st & (DEPTH - 1);
        int j = jw + 2 * st;
        const float* k0s = (j == lp)     ? (newk + l * 4)
                          : (cache_k + cbase + (size_t)j * (NKV * HD) + l * 4);
        const float* k1s = (j + 1 == lp) ? (newk + l * 4)
                          : (cache_k + cbase + (size_t)(j + 1) * (NKV * HD) + l * 4);
        const float* v0s = (j == lp)     ? (newv + l * 4)
                          : (cache_v + cbase + (size_t)j * (NKV * HD) + l * 4);
        const float* v1s = (j + 1 == lp) ? (newv + l * 4)
                          : (cache_v + cbase + (size_t)(j + 1) * (NKV * HD) + l * 4);
        cp16(&kbw[(buf * 2 + 0) * 32 + l], k0s);
        cp16(&kbw[(buf * 2 + 1) * 32 + l], k1s);
        cp16(&vbw[(buf * 2 + 0) * 32 + l], v0s);
        cp16(&vbw[(buf * 2 + 1) * 32 + l], v1s);
        asm volatile("cp.async.commit_group;");
    };

    // prime 3 stages, then fill sq (overlaps with loads)
    load_stage(0);
    load_stage(1);
    load_stage(2);

    for (int i = tid; i < 4 * HD; i += 256) {
        int h = i / HD, d = i % HD;
        sq[h * HD + d] = g_q[b * (NH * HD) + (kv * 4 + h) * HD + d];
    }
    __syncthreads();   // sq visible to all warps

    float4 qr[4];
#pragma unroll
    for (int h = 0; h < 4; h++) qr[h] = *(float4*)&sq[h * HD + 4 * l];

    const float scale = 0.08838834764831845f; // 1/sqrt(128)
    float4 acc[4];
    float m[4], lsum[4];
#pragma unroll
    for (int h = 0; h < 4; h++) {
        acc[h] = make_float4(0.f, 0.f, 0.f, 0.f);
        m[h] = -1e30f;
        lsum[h] = 0.f;
    }

#pragma unroll 1
    for (int t = 0; t < NSTAGE; t++) {
        if (t < NSTAGE - 2)       asm volatile("cp.async.wait_group 2;");
        else if (t == NSTAGE - 2) asm volatile("cp.async.wait_group 1;");
        else                      asm volatile("cp.async.wait_group 0;");

        int buf = t & (DEPTH - 1);
        float4 k0r = kbw[(buf * 2 + 0) * 32 + l];
        float4 k1r = kbw[(buf * 2 + 1) * 32 + l];
        float4 v0r = vbw[(buf * 2 + 0) * 32 + l];
        float4 v1r = vbw[(buf * 2 + 1) * 32 + l];

        if (t + 3 < NSTAGE) load_stage(t + 3);   // refill; its buf was consumed at t-1

        int jb = jw + 2 * t;
        size_t row0 = cbase + (size_t)jb * (NKV * HD);
        __stcs((float4*)(out_k + row0) + l, k0r);
        __stcs((float4*)(out_k + row0 + (size_t)(NKV * HD)) + l, k1r);
        __stcs((float4*)(out_v + row0) + l, v0r);
        __stcs((float4*)(out_v + row0 + (size_t)(NKV * HD)) + l, v1r);

        float s0[4], s1[4];
#pragma unroll
        for (int h = 0; h < 4; h++) {
            s0[h] = qr[h].x * k0r.x + qr[h].y * k0r.y + qr[h].z * k0r.z + qr[h].w * k0r.w;
            s1[h] = qr[h].x * k1r.x + qr[h].y * k1r.y + qr[h].z * k1r.z + qr[h].w * k1r.w;
        }
#pragma unroll
        for (int offx = 16; offx; offx >>= 1) {
#pragma unroll
            for (int h = 0; h < 4; h++) {
                s0[h] += __shfl_xor_sync(0xffffffffu, s0[h], offx);
                s1[h] += __shfl_xor_sync(0xffffffffu, s1[h], offx);
            }
        }

        float2 mq = __ldg((const float2*)(mask + b * SEQ + jb));

#pragma unroll
        for (int h = 0; h < 4; h++) {
            float sc0 = s0[h] * scale + mq.x;
            float sc1 = s1[h] * scale + mq.y;
            float newm = fmaxf(m[h], fmaxf(sc0, sc1));
            if (newm > m[h]) {                    // warp-uniform branch
                float fac = __expf(m[h] - newm);
                lsum[h] *= fac;
                acc[h].x *= fac; acc[h].y *= fac; acc[h].z *= fac; acc[h].w *= fac;
                m[h] = newm;
            }
            float p0 = __expf(sc0 - m[h]);
            float p1 = __expf(sc1 - m[h]);
            lsum[h] += p0 + p1;
            acc[h].x = fmaf(p0, v0r.x, fmaf(p1, v1r.x, acc[h].x));
            acc[h].y = fmaf(p0, v0r.y, fmaf(p1, v1r.y, acc[h].y));
            acc[h].z = fmaf(p0, v0r.z, fmaf(p1, v1r.z, acc[h].z));
            acc[h].w = fmaf(p0, v0r.w, fmaf(p1, v1r.w, acc[h].w));
        }
    }

    // ---- combine the 8 warp partials (sacc aliases each warp's OWN kb region) ----
    float* saccw = (float*)(kb + (size_t)w * (DEPTH * 2 * 32));  // 2 KB used of 4 KB own region
#pragma unroll
    for (int h = 0; h < 4; h++)
        *(float4*)&saccw[h * HD + 4 * l] = acc[h];
    if (l == 0) {
#pragma unroll
        for (int h = 0; h < 4; h++) { smx[w][h] = m[h]; slx[w][h] = lsum[h]; }
    }
    __syncthreads();

    size_t hbase = (size_t)(b * NKV + kv) * 4;
    for (int o = tid; o < 4 * HD; o += 256) {
        int h = o / HD, d = o % HD;
        float M = -1e30f;
#pragma unroll
        for (int ww = 0; ww < 8; ww++) M = fmaxf(M, smx[ww][h]);
        float L = 0.f, s = 0.f;
#pragma unroll
        for (int ww = 0; ww < 8; ww++) {
            float fac = __expf(smx[ww][h] - M);
            s += ((float*)(kb + (size_t)ww * (DEPTH * 2 * 32)))[h * HD + d] * fac;
            L += slx[ww][h] * fac;
        }
        g_pacc[(((hbase + h) * SPLITS) + sp) * HD + d] = s;
        if (d == 0) {
            g_pm[(hbase + h) * SPLITS + sp] = M;
            g_pl[(hbase + h) * SPLITS + sp] = L;
        }
    }
}

// ---------------- combine split partials ----------------
// grid (NH, BS), 128 threads; pm/pl are contiguous per head now.
__global__ void combine_kernel() {
    int h = blockIdx.x, b = blockIdx.y, d = threadIdx.x;
    int kv = h >> 2, r = h & 3;
    size_t hb = ((size_t)(b * NKV + kv) * 4 + r);

    float M = -1e30f;
#pragma unroll
    for (int s = 0; s < SPLITS; s++) M = fmaxf(M, g_pm[hb * SPLITS + s]);
    float L = 0.f, acc = 0.f;
#pragma unroll
    for (int s = 0; s < SPLITS; s++) {
        float wgt = __expf(g_pm[hb * SPLITS + s] - M);
        L += g_pl[hb * SPLITS + s] * wgt;
        acc = fmaf(g_pacc[(hb * SPLITS + s) * HD + d], wgt, acc);
    }
    g_attn[b * (NH * HD) + h * HD + d] = acc / L;
}

// ---------------- reduce wo-GEMM partials -> final out ----------------
__global__ void reduce_out_kernel(float* __restrict__ out) {
    int i = (blockIdx.x * 256 + threadIdx.x) * 4;
    float4 s = make_float4(0.f, 0.f, 0.f, 0.f);
#pragma unroll
    for (int ks = 0; ks < KSPLIT; ks++) {
        float4 p = *(const float4*)&g_opart[ks][i];
        s.x += p.x; s.y += p.y; s.z += p.z; s.w += p.w;
    }
    *(float4*)(out + i) = s;
}

// ---------------- launch ----------------
extern "C" void kernel_launch(void* const* d_in, const int* in_sizes, int n_in,
                              void* d_out, int out_size) {
    const float* x       = (const float*)d_in[0];
    const float* mask    = (const float*)d_in[1];
    const float* rope    = (const float*)d_in[2];
    const float* wq      = (const float*)d_in[3];
    const float* wk      = (const float*)d_in[4];
    const float* wv      = (const float*)d_in[5];
    const float* wo      = (const float*)d_in[6];
    const float* cache_k = (const float*)d_in[7];
    const float* cache_v = (const float*)d_in[8];
    const int*   last_pos = (const int*)d_in[9];

    float* out   = (float*)d_out;
    float* out_k = out + (size_t)BS * HIDDEN;
    float* out_v = out_k + (size_t)BS * SEQ * NKV * HD;

    // dyn smem: 64 KB ring buffers + 2 KB sq
    const int smem_bytes = 2 * 8 * DEPTH * 2 * 32 * 16 + 4 * HD * 4;
    static int attr_set = 0;
    if (!attr_set) {
        cudaFuncSetAttribute(attn_kernel, cudaFuncAttributeMaxDynamicSharedMemorySize, smem_bytes);
        attr_set = 1;
    }

    qkv_gemm_kernel<<<dim3(QKV_N / 128, KSPLIT), 128>>>(x, wq, wk, wv);
    rope_reduce_kernel<<<(BS * QKV_N / 2) / 256, 256>>>(rope, last_pos);
    attn_kernel<<<dim3(SPLITS, NKV, BS), 256, smem_bytes>>>(cache_k, cache_v, mask, last_pos, out_k, out_v);
    combine_kernel<<<dim3(NH, BS), HD>>>();
    wo_gemm_kernel<<<dim3(HIDDEN / 128, KSPLIT), 128>>>(wo);
    reduce_out_kernel<<<(BS * HIDDEN / 4) / 256, 256>>>(out);
}